// round 5
// baseline (speedup 1.0000x reference)
#include <cuda_runtime.h>
#include <cstdint>
#include <cstddef>

#define B_DIM 2048
#define IN_F  512
#define OUT_F 512
#define KF    22
#define KTOT  (IN_F * KF)        // 11264
#define NCOEF 20

#define G0        (-1.5f)
#define STEPF     ((float)(3.125 / 24.0))
#define INV_STEP  ((float)(24.0 / 3.125))

// ---- GEMM tiling: CTA 128x128, 8 warps (2x4), warp 64x32, KT=32, 4 stages ----
#define MT 128
#define NT 128
#define KT 32
#define KSPLIT 2
#define KCH (KTOT / KSPLIT)      // 5632
#define NIT (KCH / KT)           // 176

#define ROWB   144               // padded row: 36 floats (32 data + 4 pad)
#define A_BYTES (MT * ROWB)      // 18432
#define B_BYTES (NT * ROWB)      // 18432
#define STG    (A_BYTES + B_BYTES)
#define NSTAGE 4
#define SMEM_TOTAL (NSTAGE * STG)   // 147456

__device__ __align__(16) float g_feat[(size_t)B_DIM * KTOT];
__device__ __align__(16) float g_w[(size_t)OUT_F * KTOT];
__device__ __align__(16) float g_partial[(size_t)KSPLIT * B_DIM * OUT_F];

__device__ __forceinline__ float tf32r(float v) {
    uint32_t o;
    asm("cvt.rna.tf32.f32 %0, %1;" : "=r"(o) : "f"(v));
    return __uint_as_float(o);
}
__device__ __forceinline__ uint32_t smem_u32(const void* p) {
    uint32_t a;
    asm("{ .reg .u64 t; cvta.to.shared.u64 t, %1; cvt.u32.u64 %0, t; }" : "=r"(a) : "l"(p));
    return a;
}
__device__ __forceinline__ void cpa16(uint32_t s, const void* g) {
    asm volatile("cp.async.cg.shared.global [%0], [%1], 16;" :: "r"(s), "l"(g));
}
__device__ __forceinline__ void mma_tf32(float* c, const uint32_t* a, const uint32_t* b) {
    asm volatile(
        "mma.sync.aligned.m16n8k8.row.col.f32.tf32.tf32.f32 "
        "{%0,%1,%2,%3}, {%4,%5,%6,%7}, {%8,%9}, {%0,%1,%2,%3};"
        : "+f"(c[0]), "+f"(c[1]), "+f"(c[2]), "+f"(c[3])
        : "r"(a[0]), "r"(a[1]), "r"(a[2]), "r"(a[3]), "r"(b[0]), "r"(b[1]));
}

// ---------- kernel 1: feat[b, j*22 + f] = [neg, pos, basis_0..19] ----------
__global__ __launch_bounds__(512) void feat_kernel(const float* __restrict__ x) {
    const int b = blockIdx.x;
    const int j = threadIdx.x;
    float xv = x[b * IN_F + j];
    float xc = fminf(fmaxf(xv, -1.0f), 1.0f);
    float pos = fmaxf(xc, 0.0f);
    float neg = xc - pos;

    float* dst = g_feat + (size_t)b * KTOT + j * KF;
    dst[0] = tf32r(neg);
    dst[1] = tf32r(pos);
    #pragma unroll
    for (int q = 0; q < NCOEF; q++) dst[2 + q] = 0.0f;

    int m = (int)floorf((xc - G0) * INV_STEP);
    m = min(19, max(3, m));

    const float RK[5] = {0.0f, (float)(24.0 / 3.125), (float)(24.0 / 6.25),
                         (float)(24.0 / 9.375), (float)(24.0 / 12.5)};
    float bb[5];
    bb[0] = 1.0f;
    #pragma unroll
    for (int k = 1; k <= 4; k++) {
        float nb[5];
        #pragma unroll
        for (int t = 0; t < 5; t++) {
            if (t > k) { nb[t] = 0.0f; continue; }
            int i = m - k + t;
            float gi   = G0 + (float)i * STEPF;
            float gik1 = G0 + (float)(i + k + 1) * STEPF;
            float v = 0.0f;
            if (t > 0) v += (xc - gi) * RK[k] * bb[t - 1];
            if (t < k) v += (gik1 - xc) * RK[k] * bb[t];
            nb[t] = v;
        }
        #pragma unroll
        for (int t = 0; t < 5; t++) bb[t] = nb[t];
    }
    #pragma unroll
    for (int t = 0; t < 5; t++) {
        int idx = m - 4 + t;
        if (idx >= 0) dst[2 + idx] = tf32r(bb[t]);
    }
}

// ---------- kernel 2: W[i, j*22 + f] = [bw*pw, bw, sw*coef_0..19] ----------
__global__ __launch_bounds__(512) void w_kernel(const float* __restrict__ pw,
                                                const float* __restrict__ bw,
                                                const float* __restrict__ sw,
                                                const float* __restrict__ coef) {
    const int i = blockIdx.x;
    const int j = threadIdx.x;
    const int ij = i * IN_F + j;
    float bwv = bw[ij], pwv = pw[ij], swv = sw[ij];
    float* dst = g_w + (size_t)i * KTOT + j * KF;
    dst[0] = tf32r(bwv * pwv);
    dst[1] = tf32r(bwv);
    const float4* c4 = (const float4*)(coef + (size_t)ij * NCOEF);
    #pragma unroll
    for (int q = 0; q < 5; q++) {
        float4 c = c4[q];
        dst[2 + q * 4 + 0] = tf32r(swv * c.x);
        dst[2 + q * 4 + 1] = tf32r(swv * c.y);
        dst[2 + q * 4 + 2] = tf32r(swv * c.z);
        dst[2 + q * 4 + 3] = tf32r(swv * c.w);
    }
}

// ---------- kernel 3: mma.sync tf32 GEMM with cp.async 4-stage pipeline ----------
__global__ __launch_bounds__(256) void gemm_kernel() {
    extern __shared__ char smem[];
    const uint32_t sb = smem_u32(smem);
    const int tid  = threadIdx.x;
    const int lane = tid & 31;
    const int warp = tid >> 5;
    const int wm = warp & 1;     // 0..1  (M)
    const int wn = warp >> 1;    // 0..3  (N)
    const int lr = lane >> 2;    // 0..7
    const int lc = lane & 3;     // 0..3
    const int bm = blockIdx.x, bn = blockIdx.y, ks = blockIdx.z;

    const char* Abase = (const char*)(g_feat + (size_t)bm * MT * KTOT + (size_t)ks * KCH);
    const char* Bbase = (const char*)(g_w    + (size_t)bn * NT * KTOT + (size_t)ks * KCH);

    // per-thread load assignment: 4 A chunks + 4 B chunks of 16B per stage
    // chunk ch (0..1023): row = ch>>3, c = ch&7
    #define LOAD_STAGE(it) do {                                                    \
        const int buf_ = (it) % NSTAGE;                                            \
        const uint32_t as_ = sb + buf_ * STG;                                      \
        const uint32_t bs_ = as_ + A_BYTES;                                        \
        _Pragma("unroll")                                                          \
        for (int n_ = 0; n_ < 4; n_++) {                                           \
            int ch_ = tid + n_ * 256;                                              \
            int row_ = ch_ >> 3, c_ = ch_ & 7;                                     \
            cpa16(as_ + row_ * ROWB + c_ * 16,                                     \
                  Abase + ((size_t)row_ * KTOT + (size_t)(it) * KT) * 4 + c_ * 16);\
            cpa16(bs_ + row_ * ROWB + c_ * 16,                                     \
                  Bbase + ((size_t)row_ * KTOT + (size_t)(it) * KT) * 4 + c_ * 16);\
        }                                                                          \
        asm volatile("cp.async.commit_group;" ::: "memory");                       \
    } while (0)

    float acc[4][4][4];
    #pragma unroll
    for (int mt = 0; mt < 4; mt++)
        #pragma unroll
        for (int nt = 0; nt < 4; nt++)
            #pragma unroll
            for (int q = 0; q < 4; q++) acc[mt][nt][q] = 0.0f;

    LOAD_STAGE(0);
    LOAD_STAGE(1);
    LOAD_STAGE(2);

    const int a_r0 = wm * 64 + lr;
    const int b_r0 = wn * 32 + lr;

    for (int it = 0; it < NIT; it++) {
        asm volatile("cp.async.wait_group 2;" ::: "memory");
        __syncthreads();

        // issue next stage's loads first (overlap with compute)
        if (it + 3 < NIT) LOAD_STAGE(it + 3);
        else              asm volatile("cp.async.commit_group;" ::: "memory");

        const int buf = it % NSTAGE;
        const char* aB = smem + buf * STG;
        const char* bB = smem + buf * STG + A_BYTES;

        #pragma unroll
        for (int kk = 0; kk < KT; kk += 8) {
            const int kc = (kk + lc) * 4;   // byte offset of tf32 col
            uint32_t af[4][4], bf[4][2];
            #pragma unroll
            for (int mt = 0; mt < 4; mt++) {
                const char* p = aB + (a_r0 + mt * 16) * ROWB + kc;
                af[mt][0] = *(const uint32_t*)(p);
                af[mt][1] = *(const uint32_t*)(p + 8 * ROWB);
                af[mt][2] = *(const uint32_t*)(p + 16);
                af[mt][3] = *(const uint32_t*)(p + 8 * ROWB + 16);
            }
            #pragma unroll
            for (int nt = 0; nt < 4; nt++) {
                const char* p = bB + (b_r0 + nt * 8) * ROWB + kc;
                bf[nt][0] = *(const uint32_t*)(p);
                bf[nt][1] = *(const uint32_t*)(p + 16);
            }
            #pragma unroll
            for (int mt = 0; mt < 4; mt++)
                #pragma unroll
                for (int nt = 0; nt < 4; nt++)
                    mma_tf32(acc[mt][nt], af[mt], bf[nt]);
        }
        __syncthreads();
    }

    // epilogue: write partial sums
    float* base = g_partial + (size_t)ks * B_DIM * OUT_F;
    #pragma unroll
    for (int mt = 0; mt < 4; mt++) {
        #pragma unroll
        for (int nt = 0; nt < 4; nt++) {
            int row = bm * MT + wm * 64 + mt * 16 + lr;
            int col = bn * NT + wn * 32 + nt * 8 + 2 * lc;
            float2 v0 = make_float2(acc[mt][nt][0], acc[mt][nt][1]);
            float2 v1 = make_float2(acc[mt][nt][2], acc[mt][nt][3]);
            *(float2*)(base + (size_t)row * OUT_F + col) = v0;
            *(float2*)(base + (size_t)(row + 8) * OUT_F + col) = v1;
        }
    }
}

// ---------- kernel 4: deterministic 2-way reduce ----------
__global__ __launch_bounds__(256) void reduce_kernel(float* __restrict__ out) {
    const size_t n4 = (size_t)B_DIM * OUT_F / 4;
    size_t idx = (size_t)blockIdx.x * 256 + threadIdx.x;
    const float4* p = (const float4*)g_partial;
    float4 a = p[idx], b = p[idx + n4];
    float4 r;
    r.x = a.x + b.x;
    r.y = a.y + b.y;
    r.z = a.z + b.z;
    r.w = a.w + b.w;
    ((float4*)out)[idx] = r;
}

extern "C" void kernel_launch(void* const* d_in, const int* in_sizes, int n_in,
                              void* d_out, int out_size) {
    const float* x    = (const float*)d_in[0];
    const float* pw   = (const float*)d_in[1];
    const float* bw   = (const float*)d_in[2];
    const float* sw   = (const float*)d_in[3];
    const float* coef = (const float*)d_in[4];
    float* out = (float*)d_out;

    feat_kernel<<<B_DIM, IN_F>>>(x);
    w_kernel<<<OUT_F, IN_F>>>(pw, bw, sw, coef);

    cudaFuncSetAttribute(gemm_kernel, cudaFuncAttributeMaxDynamicSharedMemorySize, SMEM_TOTAL);
    dim3 grid(B_DIM / MT, OUT_F / NT, KSPLIT);
    gemm_kernel<<<grid, 256, SMEM_TOTAL>>>();

    reduce_kernel<<<(B_DIM * OUT_F / 4) / 256, 256>>>(out);
}

// round 6
// speedup vs baseline: 1.3457x; 1.3457x over previous
#include <cuda_runtime.h>
#include <cstdint>
#include <cstddef>

#define B_DIM 2048
#define IN_F  512
#define OUT_F 512
#define KF    22
#define KTOT  (IN_F * KF)        // 11264
#define NCOEF 20

#define G0        (-1.5f)
#define STEPF     ((float)(3.125 / 24.0))
#define INV_STEP  ((float)(24.0 / 3.125))

// ---- GEMM tiling: CTA 128x128, 8 warps (2x4), warp 64x32, KT=32, 4 stages ----
#define MT 128
#define NT 128
#define KT 32
#define KSPLIT 2
#define KCH (KTOT / KSPLIT)      // 5632
#define NIT (KCH / KT)           // 176

#define ROWB   144               // padded row: 36 floats (32 data + 4 pad)
#define A_BYTES (MT * ROWB)      // 18432
#define B_BYTES (NT * ROWB)      // 18432
#define STG    (A_BYTES + B_BYTES)
#define NSTAGE 4
#define SMEM_TOTAL (NSTAGE * STG)   // 147456

__device__ __align__(16) float g_feat[(size_t)B_DIM * KTOT];
__device__ __align__(16) float g_w[(size_t)OUT_F * KTOT];
__device__ __align__(16) float g_partial[(size_t)KSPLIT * B_DIM * OUT_F];

__device__ __forceinline__ float tf32r(float v) {
    uint32_t o;
    asm("cvt.rna.tf32.f32 %0, %1;" : "=r"(o) : "f"(v));
    return __uint_as_float(o);
}
__device__ __forceinline__ uint32_t smem_u32(const void* p) {
    uint32_t a;
    asm("{ .reg .u64 t; cvta.to.shared.u64 t, %1; cvt.u32.u64 %0, t; }" : "=r"(a) : "l"(p));
    return a;
}
__device__ __forceinline__ void cpa16(uint32_t s, const void* g) {
    asm volatile("cp.async.cg.shared.global [%0], [%1], 16;" :: "r"(s), "l"(g));
}
__device__ __forceinline__ void ldsm_x4(uint32_t* r, uint32_t addr) {
    asm volatile("ldmatrix.sync.aligned.m8n8.x4.shared.b16 {%0,%1,%2,%3}, [%4];"
                 : "=r"(r[0]), "=r"(r[1]), "=r"(r[2]), "=r"(r[3]) : "r"(addr));
}
__device__ __forceinline__ void ldsm_x2(uint32_t* r, uint32_t addr) {
    asm volatile("ldmatrix.sync.aligned.m8n8.x2.shared.b16 {%0,%1}, [%2];"
                 : "=r"(r[0]), "=r"(r[1]) : "r"(addr));
}
__device__ __forceinline__ void mma_tf32(float* c, const uint32_t* a, const uint32_t* b) {
    asm volatile(
        "mma.sync.aligned.m16n8k8.row.col.f32.tf32.tf32.f32 "
        "{%0,%1,%2,%3}, {%4,%5,%6,%7}, {%8,%9}, {%0,%1,%2,%3};"
        : "+f"(c[0]), "+f"(c[1]), "+f"(c[2]), "+f"(c[3])
        : "r"(a[0]), "r"(a[1]), "r"(a[2]), "r"(a[3]), "r"(b[0]), "r"(b[1]));
}

// ---------- kernel 1: feat[b, j*22 + f] = [neg, pos, basis_0..19] ----------
__global__ __launch_bounds__(512) void feat_kernel(const float* __restrict__ x) {
    __shared__ float row[KTOT];
    const int b = blockIdx.x;
    const int j = threadIdx.x;
    float xv = x[b * IN_F + j];
    float xc = fminf(fmaxf(xv, -1.0f), 1.0f);
    float pos = fmaxf(xc, 0.0f);
    float neg = xc - pos;

    float* dst = row + j * KF;
    dst[0] = tf32r(neg);
    dst[1] = tf32r(pos);
    #pragma unroll
    for (int q = 0; q < NCOEF; q++) dst[2 + q] = 0.0f;

    int m = (int)floorf((xc - G0) * INV_STEP);
    m = min(19, max(3, m));

    const float RK[5] = {0.0f, (float)(24.0 / 3.125), (float)(24.0 / 6.25),
                         (float)(24.0 / 9.375), (float)(24.0 / 12.5)};
    float bb[5];
    bb[0] = 1.0f;
    #pragma unroll
    for (int k = 1; k <= 4; k++) {
        float nb[5];
        #pragma unroll
        for (int t = 0; t < 5; t++) {
            if (t > k) { nb[t] = 0.0f; continue; }
            int i = m - k + t;
            float gi   = G0 + (float)i * STEPF;
            float gik1 = G0 + (float)(i + k + 1) * STEPF;
            float v = 0.0f;
            if (t > 0) v += (xc - gi) * RK[k] * bb[t - 1];
            if (t < k) v += (gik1 - xc) * RK[k] * bb[t];
            nb[t] = v;
        }
        #pragma unroll
        for (int t = 0; t < 5; t++) bb[t] = nb[t];
    }
    #pragma unroll
    for (int t = 0; t < 5; t++) {
        int idx = m - 4 + t;
        if (idx >= 0) dst[2 + idx] = tf32r(bb[t]);
    }
    __syncthreads();

    // coalesced float4 copy to global
    float4* gdst = (float4*)(g_feat + (size_t)b * KTOT);
    const float4* src = (const float4*)row;
    #pragma unroll
    for (int q = 0; q < KTOT / 4 / IN_F + 1; q++) {
        int idx = j + q * IN_F;
        if (idx < KTOT / 4) gdst[idx] = src[idx];
    }
}

// ---------- kernel 2: W[i, j*22 + f] = [bw*pw, bw, sw*coef_0..19] ----------
__global__ __launch_bounds__(512) void w_kernel(const float* __restrict__ pw,
                                                const float* __restrict__ bw,
                                                const float* __restrict__ sw,
                                                const float* __restrict__ coef) {
    __shared__ float row[KTOT];
    const int i = blockIdx.x;
    const int j = threadIdx.x;
    const int ij = i * IN_F + j;
    float bwv = bw[ij], pwv = pw[ij], swv = sw[ij];
    float* dst = row + j * KF;
    dst[0] = tf32r(bwv * pwv);
    dst[1] = tf32r(bwv);
    const float4* c4 = (const float4*)(coef + (size_t)ij * NCOEF);
    #pragma unroll
    for (int q = 0; q < 5; q++) {
        float4 c = c4[q];
        dst[2 + q * 4 + 0] = tf32r(swv * c.x);
        dst[2 + q * 4 + 1] = tf32r(swv * c.y);
        dst[2 + q * 4 + 2] = tf32r(swv * c.z);
        dst[2 + q * 4 + 3] = tf32r(swv * c.w);
    }
    __syncthreads();
    float4* gdst = (float4*)(g_w + (size_t)i * KTOT);
    const float4* src = (const float4*)row;
    #pragma unroll
    for (int q = 0; q < KTOT / 4 / IN_F + 1; q++) {
        int idx = j + q * IN_F;
        if (idx < KTOT / 4) gdst[idx] = src[idx];
    }
}

// ---------- kernel 3: mma.sync tf32 GEMM, ldmatrix fragments, 4-stage cp.async ----------
__global__ __launch_bounds__(256) void gemm_kernel() {
    extern __shared__ char smem[];
    const uint32_t sb = smem_u32(smem);
    const int tid  = threadIdx.x;
    const int lane = tid & 31;
    const int warp = tid >> 5;
    const int wm = warp & 1;     // 0..1  (M)
    const int wn = warp >> 1;    // 0..3  (N)
    const int lr = lane >> 2;    // 0..7
    const int lc = lane & 3;     // 0..3
    const int bm = blockIdx.x, bn = blockIdx.y, ks = blockIdx.z;

    const char* Abase = (const char*)(g_feat + (size_t)bm * MT * KTOT + (size_t)ks * KCH);
    const char* Bbase = (const char*)(g_w    + (size_t)bn * NT * KTOT + (size_t)ks * KCH);

    #define LOAD_STAGE(it) do {                                                    \
        const int buf_ = (it) % NSTAGE;                                            \
        const uint32_t as_ = sb + buf_ * STG;                                      \
        const uint32_t bs_ = as_ + A_BYTES;                                        \
        _Pragma("unroll")                                                          \
        for (int n_ = 0; n_ < 4; n_++) {                                           \
            int ch_ = tid + n_ * 256;                                              \
            int row_ = ch_ >> 3, c_ = ch_ & 7;                                     \
            cpa16(as_ + row_ * ROWB + c_ * 16,                                     \
                  Abase + ((size_t)row_ * KTOT + (size_t)(it) * KT) * 4 + c_ * 16);\
            cpa16(bs_ + row_ * ROWB + c_ * 16,                                     \
                  Bbase + ((size_t)row_ * KTOT + (size_t)(it) * KT) * 4 + c_ * 16);\
        }                                                                          \
        asm volatile("cp.async.commit_group;" ::: "memory");                       \
    } while (0)

    float acc[4][4][4];
    #pragma unroll
    for (int mt = 0; mt < 4; mt++)
        #pragma unroll
        for (int nt = 0; nt < 4; nt++)
            #pragma unroll
            for (int q = 0; q < 4; q++) acc[mt][nt][q] = 0.0f;

    LOAD_STAGE(0);
    LOAD_STAGE(1);
    LOAD_STAGE(2);

    // ldmatrix per-thread source rows/cols
    // A x4: matrices {rows 0-7, rows 8-15} x {cols 0-3, cols 4-7}
    const int a_row_in = ((lane >> 3) & 1) * 8 + (lane & 7);  // within 16-row tile
    const int a_col4   = (lane >> 4) * 16;                    // byte offset 0 or 16
    // B x2: matrices {cols 0-3, cols 4-7}, 8 n-rows each
    const int b_row_in = lane & 7;
    const int b_col4   = (((lane & 15) >> 3) & 1) * 16;

    const uint32_t a_off = (uint32_t)((wm * 64 + a_row_in) * ROWB) + a_col4;
    const uint32_t b_off = (uint32_t)(A_BYTES + (wn * 32 + b_row_in) * ROWB) + b_col4;

    for (int it = 0; it < NIT; it++) {
        asm volatile("cp.async.wait_group 2;" ::: "memory");
        __syncthreads();

        if (it + 3 < NIT) LOAD_STAGE(it + 3);
        else              asm volatile("cp.async.commit_group;" ::: "memory");

        const int buf = it % NSTAGE;
        const uint32_t a_base = sb + buf * STG + a_off;
        const uint32_t b_base = sb + buf * STG + b_off;

        #pragma unroll
        for (int kk = 0; kk < 4; kk++) {        // 4 x K=8 steps
            uint32_t af[4][4], bf[4][2];
            #pragma unroll
            for (int mt = 0; mt < 4; mt++)
                ldsm_x4(af[mt], a_base + mt * (16 * ROWB) + kk * 32);
            #pragma unroll
            for (int nt = 0; nt < 4; nt++)
                ldsm_x2(bf[nt], b_base + nt * (8 * ROWB) + kk * 32);
            #pragma unroll
            for (int mt = 0; mt < 4; mt++)
                #pragma unroll
                for (int nt = 0; nt < 4; nt++)
                    mma_tf32(acc[mt][nt], af[mt], bf[nt]);
        }
    }

    // epilogue: write partial sums
    float* base = g_partial + (size_t)ks * B_DIM * OUT_F;
    #pragma unroll
    for (int mt = 0; mt < 4; mt++) {
        #pragma unroll
        for (int nt = 0; nt < 4; nt++) {
            int row = bm * MT + wm * 64 + mt * 16 + lr;
            int col = bn * NT + wn * 32 + nt * 8 + 2 * lc;
            float2 v0 = make_float2(acc[mt][nt][0], acc[mt][nt][1]);
            float2 v1 = make_float2(acc[mt][nt][2], acc[mt][nt][3]);
            *(float2*)(base + (size_t)row * OUT_F + col) = v0;
            *(float2*)(base + (size_t)(row + 8) * OUT_F + col) = v1;
        }
    }
}

// ---------- kernel 4: deterministic 2-way reduce ----------
__global__ __launch_bounds__(256) void reduce_kernel(float* __restrict__ out) {
    const size_t n4 = (size_t)B_DIM * OUT_F / 4;
    size_t idx = (size_t)blockIdx.x * 256 + threadIdx.x;
    const float4* p = (const float4*)g_partial;
    float4 a = p[idx], b = p[idx + n4];
    float4 r;
    r.x = a.x + b.x;
    r.y = a.y + b.y;
    r.z = a.z + b.z;
    r.w = a.w + b.w;
    ((float4*)out)[idx] = r;
}

extern "C" void kernel_launch(void* const* d_in, const int* in_sizes, int n_in,
                              void* d_out, int out_size) {
    const float* x    = (const float*)d_in[0];
    const float* pw   = (const float*)d_in[1];
    const float* bw   = (const float*)d_in[2];
    const float* sw   = (const float*)d_in[3];
    const float* coef = (const float*)d_in[4];
    float* out = (float*)d_out;

    feat_kernel<<<B_DIM, IN_F>>>(x);
    w_kernel<<<OUT_F, IN_F>>>(pw, bw, sw, coef);

    cudaFuncSetAttribute(gemm_kernel, cudaFuncAttributeMaxDynamicSharedMemorySize, SMEM_TOTAL);
    dim3 grid(B_DIM / MT, OUT_F / NT, KSPLIT);
    gemm_kernel<<<grid, 256, SMEM_TOTAL>>>();

    reduce_kernel<<<(B_DIM * OUT_F / 4) / 256, 256>>>(out);
}

// round 8
// speedup vs baseline: 2.0879x; 1.5515x over previous
#include <cuda_runtime.h>
#include <cuda_fp16.h>
#include <cstdint>
#include <cstddef>

#define B_DIM 2048
#define IN_F  512
#define OUT_F 512
#define KF    22
#define KTOT  (IN_F * KF)        // 11264
#define NCOEF 20

#define G0        (-1.5f)
#define STEPF     ((float)(3.125 / 24.0))
#define INV_STEP  ((float)(24.0 / 3.125))

// ---- GEMM tiling: CTA 128x128, 8 warps (2x4), warp 64x32, KT=32 halves, 4 stages ----
#define MT 128
#define NT 128
#define KT 32
#define KSPLIT 2
#define KCH (KTOT / KSPLIT)      // 5632
#define NIT (KCH / KT)           // 176

#define ROWB   80                // 64B data + 16B pad (conflict-free LDSM)
#define A_BYTES (MT * ROWB)      // 10240
#define B_BYTES (NT * ROWB)      // 10240
#define STG    (A_BYTES + B_BYTES)
#define NSTAGE 4
#define SMEM_TOTAL (NSTAGE * STG)   // 81920

__device__ __align__(16) __half g_feat[(size_t)B_DIM * KTOT];   // 46 MB
__device__ __align__(16) __half g_w[(size_t)OUT_F * KTOT];      // 11.5 MB
__device__ __align__(16) float g_partial[(size_t)KSPLIT * B_DIM * OUT_F];

__device__ __forceinline__ uint32_t smem_u32(const void* p) {
    uint32_t a;
    asm("{ .reg .u64 t; cvta.to.shared.u64 t, %1; cvt.u32.u64 %0, t; }" : "=r"(a) : "l"(p));
    return a;
}
__device__ __forceinline__ void cpa16(uint32_t s, const void* g) {
    asm volatile("cp.async.cg.shared.global [%0], [%1], 16;" :: "r"(s), "l"(g));
}
__device__ __forceinline__ void ldsm_x4(uint32_t* r, uint32_t addr) {
    asm volatile("ldmatrix.sync.aligned.m8n8.x4.shared.b16 {%0,%1,%2,%3}, [%4];"
                 : "=r"(r[0]), "=r"(r[1]), "=r"(r[2]), "=r"(r[3]) : "r"(addr));
}
__device__ __forceinline__ void ldsm_x2(uint32_t* r, uint32_t addr) {
    asm volatile("ldmatrix.sync.aligned.m8n8.x2.shared.b16 {%0,%1}, [%2];"
                 : "=r"(r[0]), "=r"(r[1]) : "r"(addr));
}
__device__ __forceinline__ void mma_f16(float* c, const uint32_t* a, const uint32_t* b) {
    asm volatile(
        "mma.sync.aligned.m16n8k16.row.col.f32.f16.f16.f32 "
        "{%0,%1,%2,%3}, {%4,%5,%6,%7}, {%8,%9}, {%0,%1,%2,%3};"
        : "+f"(c[0]), "+f"(c[1]), "+f"(c[2]), "+f"(c[3])
        : "r"(a[0]), "r"(a[1]), "r"(a[2]), "r"(a[3]), "r"(b[0]), "r"(b[1]));
}

// ---------- kernel 1: feat[b, j*22 + f] = [neg, pos, basis_0..19] (fp16) ----------
__global__ __launch_bounds__(512) void feat_kernel(const float* __restrict__ x) {
    __shared__ __half row[KTOT];
    const int b = blockIdx.x;
    const int j = threadIdx.x;
    float xv = x[b * IN_F + j];
    float xc = fminf(fmaxf(xv, -1.0f), 1.0f);
    float pos = fmaxf(xc, 0.0f);
    float neg = xc - pos;

    __half* dst = row + j * KF;
    dst[0] = __float2half_rn(neg);
    dst[1] = __float2half_rn(pos);
    #pragma unroll
    for (int q = 0; q < NCOEF; q++) dst[2 + q] = __float2half_rn(0.0f);

    int m = (int)floorf((xc - G0) * INV_STEP);
    m = min(19, max(3, m));

    const float RK[5] = {0.0f, (float)(24.0 / 3.125), (float)(24.0 / 6.25),
                         (float)(24.0 / 9.375), (float)(24.0 / 12.5)};
    float bb[5];
    bb[0] = 1.0f;
    #pragma unroll
    for (int k = 1; k <= 4; k++) {
        float nb[5];
        #pragma unroll
        for (int t = 0; t < 5; t++) {
            if (t > k) { nb[t] = 0.0f; continue; }
            int i = m - k + t;
            float gi   = G0 + (float)i * STEPF;
            float gik1 = G0 + (float)(i + k + 1) * STEPF;
            float v = 0.0f;
            if (t > 0) v += (xc - gi) * RK[k] * bb[t - 1];
            if (t < k) v += (gik1 - xc) * RK[k] * bb[t];
            nb[t] = v;
        }
        #pragma unroll
        for (int t = 0; t < 5; t++) bb[t] = nb[t];
    }
    #pragma unroll
    for (int t = 0; t < 5; t++) {
        int idx = m - 4 + t;
        if (idx >= 0) dst[2 + idx] = __float2half_rn(bb[t]);
    }
    __syncthreads();

    // coalesced 16B copy to global (KTOT*2/16 = 2816 chunks)
    uint4* gdst = (uint4*)(g_feat + (size_t)b * KTOT);
    const uint4* src = (const uint4*)row;
    #pragma unroll
    for (int q = 0; q < 6; q++) {
        int idx = j + q * IN_F;
        if (idx < KTOT * 2 / 16) gdst[idx] = src[idx];
    }
}

// ---------- kernel 2: W[i, j*22 + f] = [bw*pw, bw, sw*coef_0..19] (fp16) ----------
__global__ __launch_bounds__(512) void w_kernel(const float* __restrict__ pw,
                                                const float* __restrict__ bw,
                                                const float* __restrict__ sw,
                                                const float* __restrict__ coef) {
    __shared__ __half row[KTOT];
    const int i = blockIdx.x;
    const int j = threadIdx.x;
    const int ij = i * IN_F + j;
    float bwv = bw[ij], pwv = pw[ij], swv = sw[ij];
    __half* dst = row + j * KF;
    dst[0] = __float2half_rn(bwv * pwv);
    dst[1] = __float2half_rn(bwv);
    const float4* c4 = (const float4*)(coef + (size_t)ij * NCOEF);
    #pragma unroll
    for (int q = 0; q < 5; q++) {
        float4 c = c4[q];
        dst[2 + q * 4 + 0] = __float2half_rn(swv * c.x);
        dst[2 + q * 4 + 1] = __float2half_rn(swv * c.y);
        dst[2 + q * 4 + 2] = __float2half_rn(swv * c.z);
        dst[2 + q * 4 + 3] = __float2half_rn(swv * c.w);
    }
    __syncthreads();
    uint4* gdst = (uint4*)(g_w + (size_t)i * KTOT);
    const uint4* src = (const uint4*)row;
    #pragma unroll
    for (int q = 0; q < 6; q++) {
        int idx = j + q * IN_F;
        if (idx < KTOT * 2 / 16) gdst[idx] = src[idx];
    }
}

// ---------- kernel 3: mma.sync fp16 GEMM, ldmatrix fragments, 4-stage cp.async ----------
__global__ __launch_bounds__(256) void gemm_kernel() {
    extern __shared__ char smem[];
    const uint32_t sb = smem_u32(smem);
    const int tid  = threadIdx.x;
    const int lane = tid & 31;
    const int warp = tid >> 5;
    const int wm = warp & 1;     // 0..1  (M)
    const int wn = warp >> 1;    // 0..3  (N)
    const int lr = lane >> 2;    // 0..7
    const int lc = lane & 3;     // 0..3
    const int bm = blockIdx.x, bn = blockIdx.y, ks = blockIdx.z;

    const char* Abase = (const char*)(g_feat + (size_t)bm * MT * KTOT + (size_t)ks * KCH);
    const char* Bbase = (const char*)(g_w    + (size_t)bn * NT * KTOT + (size_t)ks * KCH);

    // per stage: A 128 rows x 64B = 512 chunks, B 512 chunks; 2+2 per thread
    #define LOAD_STAGE(it) do {                                                    \
        const int buf_ = (it) % NSTAGE;                                            \
        const uint32_t as_ = sb + buf_ * STG;                                      \
        const uint32_t bs_ = as_ + A_BYTES;                                        \
        _Pragma("unroll")                                                          \
        for (int n_ = 0; n_ < 2; n_++) {                                           \
            int ch_ = tid + n_ * 256;                                              \
            int row_ = ch_ >> 2, c_ = ch_ & 3;                                     \
            cpa16(as_ + row_ * ROWB + c_ * 16,                                     \
                  Abase + ((size_t)row_ * KTOT + (size_t)(it) * KT) * 2 + c_ * 16);\
            cpa16(bs_ + row_ * ROWB + c_ * 16,                                     \
                  Bbase + ((size_t)row_ * KTOT + (size_t)(it) * KT) * 2 + c_ * 16);\
        }                                                                          \
        asm volatile("cp.async.commit_group;" ::: "memory");                       \
    } while (0)

    float acc[4][4][4];
    #pragma unroll
    for (int mt = 0; mt < 4; mt++)
        #pragma unroll
        for (int nt = 0; nt < 4; nt++)
            #pragma unroll
            for (int q = 0; q < 4; q++) acc[mt][nt][q] = 0.0f;

    LOAD_STAGE(0);
    LOAD_STAGE(1);
    LOAD_STAGE(2);

    // ldmatrix per-thread addresses
    const int a_row_in = ((lane >> 3) & 1) * 8 + (lane & 7);
    const int a_col16  = (lane >> 4) * 16;                 // 0 or 16 (k halves 0-7 / 8-15)
    const int b_row_in = lane & 7;
    const int b_col16  = (((lane & 15) >> 3) & 1) * 16;

    const uint32_t a_off = (uint32_t)((wm * 64 + a_row_in) * ROWB) + a_col16;
    const uint32_t b_off = (uint32_t)(A_BYTES + (wn * 32 + b_row_in) * ROWB) + b_col16;

    for (int it = 0; it < NIT; it++) {
        asm volatile("cp.async.wait_group 2;" ::: "memory");
        __syncthreads();

        if (it + 3 < NIT) LOAD_STAGE(it + 3);
        else              asm volatile("cp.async.commit_group;" ::: "memory");

        const int buf = it % NSTAGE;
        const uint32_t a_base = sb + buf * STG + a_off;
        const uint32_t b_base = sb + buf * STG + b_off;

        #pragma unroll
        for (int kk = 0; kk < 2; kk++) {        // 2 x K=16 steps (32B each)
            uint32_t af[4][4], bf[4][2];
            #pragma unroll
            for (int mt = 0; mt < 4; mt++)
                ldsm_x4(af[mt], a_base + mt * (16 * ROWB) + kk * 32);
            #pragma unroll
            for (int nt = 0; nt < 4; nt++)
                ldsm_x2(bf[nt], b_base + nt * (8 * ROWB) + kk * 32);
            #pragma unroll
            for (int mt = 0; mt < 4; mt++)
                #pragma unroll
                for (int nt = 0; nt < 4; nt++)
                    mma_f16(acc[mt][nt], af[mt], bf[nt]);
        }
    }

    // epilogue: write partial sums
    float* base = g_partial + (size_t)ks * B_DIM * OUT_F;
    #pragma unroll
    for (int mt = 0; mt < 4; mt++) {
        #pragma unroll
        for (int nt = 0; nt < 4; nt++) {
            int row = bm * MT + wm * 64 + mt * 16 + lr;
            int col = bn * NT + wn * 32 + nt * 8 + 2 * lc;
            float2 v0 = make_float2(acc[mt][nt][0], acc[mt][nt][1]);
            float2 v1 = make_float2(acc[mt][nt][2], acc[mt][nt][3]);
            *(float2*)(base + (size_t)row * OUT_F + col) = v0;
            *(float2*)(base + (size_t)(row + 8) * OUT_F + col) = v1;
        }
    }
}

// ---------- kernel 4: deterministic 2-way reduce ----------
__global__ __launch_bounds__(256) void reduce_kernel(float* __restrict__ out) {
    const size_t n4 = (size_t)B_DIM * OUT_F / 4;
    size_t idx = (size_t)blockIdx.x * 256 + threadIdx.x;
    const float4* p = (const float4*)g_partial;
    float4 a = p[idx], b = p[idx + n4];
    float4 r;
    r.x = a.x + b.x;
    r.y = a.y + b.y;
    r.z = a.z + b.z;
    r.w = a.w + b.w;
    ((float4*)out)[idx] = r;
}

extern "C" void kernel_launch(void* const* d_in, const int* in_sizes, int n_in,
                              void* d_out, int out_size) {
    const float* x    = (const float*)d_in[0];
    const float* pw   = (const float*)d_in[1];
    const float* bw   = (const float*)d_in[2];
    const float* sw   = (const float*)d_in[3];
    const float* coef = (const float*)d_in[4];
    float* out = (float*)d_out;

    feat_kernel<<<B_DIM, IN_F>>>(x);
    w_kernel<<<OUT_F, IN_F>>>(pw, bw, sw, coef);

    cudaFuncSetAttribute(gemm_kernel, cudaFuncAttributeMaxDynamicSharedMemorySize, SMEM_TOTAL);
    dim3 grid(B_DIM / MT, OUT_F / NT, KSPLIT);
    gemm_kernel<<<grid, 256, SMEM_TOTAL>>>();

    reduce_kernel<<<(B_DIM * OUT_F / 4) / 256, 256>>>(out);
}

// round 12
// speedup vs baseline: 2.4226x; 1.1603x over previous
#include <cuda_runtime.h>
#include <cuda_fp16.h>
#include <cstdint>
#include <cstddef>

#define B_DIM 2048
#define IN_F  512
#define OUT_F 512
#define KF    22
#define KTOT  (IN_F * KF)        // 11264
#define NCOEF 20

#define G0        (-1.5f)
#define STEPF     ((float)(3.125 / 24.0))
#define INV_STEP  ((float)(24.0 / 3.125))

// ---- GEMM tiling: CTA 128x256, 8 warps (2x4), warp 64x64, KT=32 halves, 4 stages ----
#define MT 128
#define NT 256
#define KT 32
#define KSPLIT 4
#define KCH (KTOT / KSPLIT)      // 2816
#define NIT (KCH / KT)           // 88

#define ROWB   80                // 64B data + 16B pad (conflict-free LDSM)
#define A_BYTES (MT * ROWB)      // 10240
#define B_BYTES (NT * ROWB)      // 20480
#define STG    (A_BYTES + B_BYTES)
#define NSTAGE 4
#define SMEM_TOTAL (NSTAGE * STG)   // 122880

__device__ __align__(16) __half g_feat[(size_t)B_DIM * KTOT];   // 46 MB
__device__ __align__(16) __half g_w[(size_t)OUT_F * KTOT];      // 11.5 MB
__device__ __align__(16) float g_partial[(size_t)KSPLIT * B_DIM * OUT_F]; // 16.8 MB

__device__ __forceinline__ uint32_t smem_u32(const void* p) {
    uint32_t a;
    asm("{ .reg .u64 t; cvta.to.shared.u64 t, %1; cvt.u32.u64 %0, t; }" : "=r"(a) : "l"(p));
    return a;
}
__device__ __forceinline__ void cpa16(uint32_t s, const void* g) {
    asm volatile("cp.async.cg.shared.global [%0], [%1], 16;" :: "r"(s), "l"(g));
}
__device__ __forceinline__ void ldsm_x4(uint32_t* r, uint32_t addr) {
    asm volatile("ldmatrix.sync.aligned.m8n8.x4.shared.b16 {%0,%1,%2,%3}, [%4];"
                 : "=r"(r[0]), "=r"(r[1]), "=r"(r[2]), "=r"(r[3]) : "r"(addr));
}
__device__ __forceinline__ void mma_f16(float* c, const uint32_t* a, const uint32_t* b) {
    asm volatile(
        "mma.sync.aligned.m16n8k16.row.col.f32.f16.f16.f32 "
        "{%0,%1,%2,%3}, {%4,%5,%6,%7}, {%8,%9}, {%0,%1,%2,%3};"
        : "+f"(c[0]), "+f"(c[1]), "+f"(c[2]), "+f"(c[3])
        : "r"(a[0]), "r"(a[1]), "r"(a[2]), "r"(a[3]), "r"(b[0]), "r"(b[1]));
}

// ---------- kernel 1: feat[b, j*22 + f] = [neg, pos, basis_0..19] (fp16) ----------
__global__ __launch_bounds__(512) void feat_kernel(const float* __restrict__ x) {
    __shared__ __half row[KTOT];
    const int b = blockIdx.x;
    const int j = threadIdx.x;
    float xv = x[b * IN_F + j];
    float xc = fminf(fmaxf(xv, -1.0f), 1.0f);
    float pos = fmaxf(xc, 0.0f);
    float neg = xc - pos;

    __half* dst = row + j * KF;
    dst[0] = __float2half_rn(neg);
    dst[1] = __float2half_rn(pos);
    #pragma unroll
    for (int q = 0; q < NCOEF; q++) dst[2 + q] = __float2half_rn(0.0f);

    int m = (int)floorf((xc - G0) * INV_STEP);
    m = min(19, max(3, m));

    const float RK[5] = {0.0f, (float)(24.0 / 3.125), (float)(24.0 / 6.25),
                         (float)(24.0 / 9.375), (float)(24.0 / 12.5)};
    float bb[5];
    bb[0] = 1.0f;
    #pragma unroll
    for (int k = 1; k <= 4; k++) {
        float nb[5];
        #pragma unroll
        for (int t = 0; t < 5; t++) {
            if (t > k) { nb[t] = 0.0f; continue; }
            int i = m - k + t;
            float gi   = G0 + (float)i * STEPF;
            float gik1 = G0 + (float)(i + k + 1) * STEPF;
            float v = 0.0f;
            if (t > 0) v += (xc - gi) * RK[k] * bb[t - 1];
            if (t < k) v += (gik1 - xc) * RK[k] * bb[t];
            nb[t] = v;
        }
        #pragma unroll
        for (int t = 0; t < 5; t++) bb[t] = nb[t];
    }
    #pragma unroll
    for (int t = 0; t < 5; t++) {
        int idx = m - 4 + t;
        if (idx >= 0) dst[2 + idx] = __float2half_rn(bb[t]);
    }
    __syncthreads();

    uint4* gdst = (uint4*)(g_feat + (size_t)b * KTOT);
    const uint4* src = (const uint4*)row;
    #pragma unroll
    for (int q = 0; q < 6; q++) {
        int idx = j + q * IN_F;
        if (idx < KTOT * 2 / 16) gdst[idx] = src[idx];
    }
}

// ---------- kernel 2: W[i, j*22 + f] = [bw*pw, bw, sw*coef_0..19] (fp16) ----------
__global__ __launch_bounds__(512) void w_kernel(const float* __restrict__ pw,
                                                const float* __restrict__ bw,
                                                const float* __restrict__ sw,
                                                const float* __restrict__ coef) {
    __shared__ __half row[KTOT];
    const int i = blockIdx.x;
    const int j = threadIdx.x;
    const int ij = i * IN_F + j;
    float bwv = bw[ij], pwv = pw[ij], swv = sw[ij];
    __half* dst = row + j * KF;
    dst[0] = __float2half_rn(bwv * pwv);
    dst[1] = __float2half_rn(bwv);
    const float4* c4 = (const float4*)(coef + (size_t)ij * NCOEF);
    #pragma unroll
    for (int q = 0; q < 5; q++) {
        float4 c = c4[q];
        dst[2 + q * 4 + 0] = __float2half_rn(swv * c.x);
        dst[2 + q * 4 + 1] = __float2half_rn(swv * c.y);
        dst[2 + q * 4 + 2] = __float2half_rn(swv * c.z);
        dst[2 + q * 4 + 3] = __float2half_rn(swv * c.w);
    }
    __syncthreads();
    uint4* gdst = (uint4*)(g_w + (size_t)i * KTOT);
    const uint4* src = (const uint4*)row;
    #pragma unroll
    for (int q = 0; q < 6; q++) {
        int idx = j + q * IN_F;
        if (idx < KTOT * 2 / 16) gdst[idx] = src[idx];
    }
}

// ---------- kernel 3: mma.sync fp16 GEMM, warp 64x64, ldmatrix x4, 4-stage cp.async ----------
__global__ __launch_bounds__(256) void gemm_kernel() {
    extern __shared__ char smem[];
    const uint32_t sb = smem_u32(smem);
    const int tid  = threadIdx.x;
    const int lane = tid & 31;
    const int warp = tid >> 5;
    const int wm = warp >> 2;    // 0..1  (M)
    const int wn = warp & 3;     // 0..3  (N)
    const int lr = lane >> 2;    // 0..7
    const int lc = lane & 3;     // 0..3
    const int bm = blockIdx.x, bn = blockIdx.y, ks = blockIdx.z;

    const char* Abase = (const char*)(g_feat + (size_t)bm * MT * KTOT + (size_t)ks * KCH);
    const char* Bbase = (const char*)(g_w    + (size_t)bn * NT * KTOT + (size_t)ks * KCH);

    // per stage: A 128 rows x 4 chunks = 512, B 256 x 4 = 1024; 2+4 per thread
    #define LOAD_STAGE(it) do {                                                    \
        const int buf_ = (it) % NSTAGE;                                            \
        const uint32_t as_ = sb + buf_ * STG;                                      \
        const uint32_t bs_ = as_ + A_BYTES;                                        \
        _Pragma("unroll")                                                          \
        for (int n_ = 0; n_ < 2; n_++) {                                           \
            int ch_ = tid + n_ * 256;                                              \
            int row_ = ch_ >> 2, c_ = ch_ & 3;                                     \
            cpa16(as_ + row_ * ROWB + c_ * 16,                                     \
                  Abase + ((size_t)row_ * KTOT + (size_t)(it) * KT) * 2 + c_ * 16);\
        }                                                                          \
        _Pragma("unroll")                                                          \
        for (int n_ = 0; n_ < 4; n_++) {                                           \
            int ch_ = tid + n_ * 256;                                              \
            int row_ = ch_ >> 2, c_ = ch_ & 3;                                     \
            cpa16(bs_ + row_ * ROWB + c_ * 16,                                     \
                  Bbase + ((size_t)row_ * KTOT + (size_t)(it) * KT) * 2 + c_ * 16);\
        }                                                                          \
        asm volatile("cp.async.commit_group;" ::: "memory");                       \
    } while (0)

    float acc[4][8][4];
    #pragma unroll
    for (int mt = 0; mt < 4; mt++)
        #pragma unroll
        for (int nt = 0; nt < 8; nt++)
            #pragma unroll
            for (int q = 0; q < 4; q++) acc[mt][nt][q] = 0.0f;

    LOAD_STAGE(0);
    LOAD_STAGE(1);
    LOAD_STAGE(2);

    // A x4 per-thread address: matrices [r0-7 k0-7, r8-15 k0-7, r0-7 k8-15, r8-15 k8-15]
    const int a_row_in = ((lane >> 3) & 1) * 8 + (lane & 7);
    const int a_col16  = (lane >> 4) * 16;
    // B x4: matrices [n0-7 k0-7, n0-7 k8-15, n8-15 k0-7, n8-15 k8-15]
    //   -> regs {r0,r1} = n-tile0 frag, {r2,r3} = n-tile1 frag
    const int b_g      = lane >> 3;                   // 0..3
    const int b_row_in = (b_g >> 1) * 8 + (lane & 7);
    const int b_col16  = (b_g & 1) * 16;

    const uint32_t a_off = (uint32_t)((wm * 64 + a_row_in) * ROWB) + a_col16;
    const uint32_t b_off = (uint32_t)(A_BYTES + (wn * 64 + b_row_in) * ROWB) + b_col16;

    for (int it = 0; it < NIT; it++) {
        asm volatile("cp.async.wait_group 2;" ::: "memory");
        __syncthreads();

        if (it + 3 < NIT) LOAD_STAGE(it + 3);
        else              asm volatile("cp.async.commit_group;" ::: "memory");

        const int buf = it % NSTAGE;
        const uint32_t a_base = sb + buf * STG + a_off;
        const uint32_t b_base = sb + buf * STG + b_off;

        #pragma unroll
        for (int kk = 0; kk < 2; kk++) {        // 2 x K=16 steps (32B each)
            uint32_t af[4][4], bf[4][4];
            #pragma unroll
            for (int mt = 0; mt < 4; mt++)
                ldsm_x4(af[mt], a_base + mt * (16 * ROWB) + kk * 32);
            #pragma unroll
            for (int np = 0; np < 4; np++)      // each covers 2 n8 tiles
                ldsm_x4(bf[np], b_base + np * (16 * ROWB) + kk * 32);
            #pragma unroll
            for (int mt = 0; mt < 4; mt++)
                #pragma unroll
                for (int nt = 0; nt < 8; nt++)
                    mma_f16(acc[mt][nt], af[mt], &bf[nt >> 1][(nt & 1) * 2]);
        }
    }

    // epilogue: write partial sums
    float* base = g_partial + (size_t)ks * B_DIM * OUT_F;
    #pragma unroll
    for (int mt = 0; mt < 4; mt++) {
        #pragma unroll
        for (int nt = 0; nt < 8; nt++) {
            int row = bm * MT + wm * 64 + mt * 16 + lr;
            int col = bn * NT + wn * 64 + nt * 8 + 2 * lc;
            float2 v0 = make_float2(acc[mt][nt][0], acc[mt][nt][1]);
            float2 v1 = make_float2(acc[mt][nt][2], acc[mt][nt][3]);
            *(float2*)(base + (size_t)row * OUT_F + col) = v0;
            *(float2*)(base + (size_t)(row + 8) * OUT_F + col) = v1;
        }
    }
}

// ---------- kernel 4: deterministic 4-way reduce ----------
__global__ __launch_bounds__(256) void reduce_kernel(float* __restrict__ out) {
    const size_t n4 = (size_t)B_DIM * OUT_F / 4;
    size_t idx = (size_t)blockIdx.x * 256 + threadIdx.x;
    const float4* p = (const float4*)g_partial;
    float4 a = p[idx], b = p[idx + n4], c = p[idx + 2 * n4], d = p[idx + 3 * n4];
    float4 r;
    r.x = (a.x + b.x) + (c.x + d.x);
    r.y = (a.y + b.y) + (c.y + d.y);
    r.z = (a.z + b.z) + (c.z + d.z);
    r.w = (a.w + b.w) + (c.w + d.w);
    ((float4*)out)[idx] = r;
}

extern "C" void kernel_launch(void* const* d_in, const int* in_sizes, int n_in,
                              void* d_out, int out_size) {
    const float* x    = (const float*)d_in[0];
    const float* pw   = (const float*)d_in[1];
    const float* bw   = (const float*)d_in[2];
    const float* sw   = (const float*)d_in[3];
    const float* coef = (const float*)d_in[4];
    float* out = (float*)d_out;

    feat_kernel<<<B_DIM, IN_F>>>(x);
    w_kernel<<<OUT_F, IN_F>>>(pw, bw, sw, coef);

    cudaFuncSetAttribute(gemm_kernel, cudaFuncAttributeMaxDynamicSharedMemorySize, SMEM_TOTAL);
    dim3 grid(B_DIM / MT, OUT_F / NT, KSPLIT);
    gemm_kernel<<<grid, 256, SMEM_TOTAL>>>();

    reduce_kernel<<<(B_DIM * OUT_F / 4) / 256, 256>>>(out);
}

// round 13
// speedup vs baseline: 2.8208x; 1.1643x over previous
#include <cuda_runtime.h>
#include <cuda_fp16.h>
#include <cstdint>
#include <cstddef>

#define B_DIM 2048
#define IN_F  512
#define OUT_F 512
#define KF    22
#define KTOT  (IN_F * KF)        // 11264
#define NCOEF 20

#define G0        (-1.5f)
#define STEPF     ((float)(3.125 / 24.0))
#define INV_STEP  ((float)(24.0 / 3.125))

// ---- GEMM tiling: CTA 128x256, 8 warps (2x4), warp 64x64, KT=64 halves, 3 stages ----
#define MT 128
#define NT 256
#define KT 64
#define KSPLIT 4
#define KCH (KTOT / KSPLIT)      // 2816
#define NIT (KCH / KT)           // 44

#define ROWB   144               // 128B data + 16B pad (conflict-free LDSM)
#define A_BYTES (MT * ROWB)      // 18432
#define B_BYTES (NT * ROWB)      // 36864
#define STG    (A_BYTES + B_BYTES)   // 55296
#define NSTAGE 3
#define SMEM_TOTAL (NSTAGE * STG)    // 165888

__device__ __align__(16) __half g_feat[(size_t)B_DIM * KTOT];   // 46 MB
__device__ __align__(16) __half g_w[(size_t)OUT_F * KTOT];      // 11.5 MB
__device__ __align__(16) float g_partial[(size_t)KSPLIT * B_DIM * OUT_F]; // 16.8 MB

__device__ __forceinline__ uint32_t smem_u32(const void* p) {
    uint32_t a;
    asm("{ .reg .u64 t; cvta.to.shared.u64 t, %1; cvt.u32.u64 %0, t; }" : "=r"(a) : "l"(p));
    return a;
}
__device__ __forceinline__ void cpa16(uint32_t s, const void* g) {
    asm volatile("cp.async.cg.shared.global [%0], [%1], 16;" :: "r"(s), "l"(g));
}
__device__ __forceinline__ void ldsm_x4(uint32_t* r, uint32_t addr) {
    asm volatile("ldmatrix.sync.aligned.m8n8.x4.shared.b16 {%0,%1,%2,%3}, [%4];"
                 : "=r"(r[0]), "=r"(r[1]), "=r"(r[2]), "=r"(r[3]) : "r"(addr));
}
__device__ __forceinline__ void mma_f16(float* c, const uint32_t* a, const uint32_t* b) {
    asm volatile(
        "mma.sync.aligned.m16n8k16.row.col.f32.f16.f16.f32 "
        "{%0,%1,%2,%3}, {%4,%5,%6,%7}, {%8,%9}, {%0,%1,%2,%3};"
        : "+f"(c[0]), "+f"(c[1]), "+f"(c[2]), "+f"(c[3])
        : "r"(a[0]), "r"(a[1]), "r"(a[2]), "r"(a[3]), "r"(b[0]), "r"(b[1]));
}

// ---------- kernel 1: fused prep. blocks [0,2048): feat; [2048,2560): W ----------
__global__ __launch_bounds__(512) void prep_kernel(const float* __restrict__ x,
                                                   const float* __restrict__ pw,
                                                   const float* __restrict__ bw,
                                                   const float* __restrict__ sw,
                                                   const float* __restrict__ coef) {
    __shared__ __half row[KTOT];
    const int j = threadIdx.x;

    if (blockIdx.x < B_DIM) {
        const int b = blockIdx.x;
        float xv = x[b * IN_F + j];
        float xc = fminf(fmaxf(xv, -1.0f), 1.0f);
        float pos = fmaxf(xc, 0.0f);
        float neg = xc - pos;

        __half* dst = row + j * KF;
        dst[0] = __float2half_rn(neg);
        dst[1] = __float2half_rn(pos);
        #pragma unroll
        for (int q = 0; q < NCOEF; q++) dst[2 + q] = __float2half_rn(0.0f);

        int m = (int)floorf((xc - G0) * INV_STEP);
        m = min(19, max(3, m));

        const float RK[5] = {0.0f, (float)(24.0 / 3.125), (float)(24.0 / 6.25),
                             (float)(24.0 / 9.375), (float)(24.0 / 12.5)};
        float bb[5];
        bb[0] = 1.0f;
        #pragma unroll
        for (int k = 1; k <= 4; k++) {
            float nb[5];
            #pragma unroll
            for (int t = 0; t < 5; t++) {
                if (t > k) { nb[t] = 0.0f; continue; }
                int i = m - k + t;
                float gi   = G0 + (float)i * STEPF;
                float gik1 = G0 + (float)(i + k + 1) * STEPF;
                float v = 0.0f;
                if (t > 0) v += (xc - gi) * RK[k] * bb[t - 1];
                if (t < k) v += (gik1 - xc) * RK[k] * bb[t];
                nb[t] = v;
            }
            #pragma unroll
            for (int t = 0; t < 5; t++) bb[t] = nb[t];
        }
        #pragma unroll
        for (int t = 0; t < 5; t++) {
            int idx = m - 4 + t;
            if (idx >= 0) dst[2 + idx] = __float2half_rn(bb[t]);
        }
        __syncthreads();

        uint4* gdst = (uint4*)(g_feat + (size_t)b * KTOT);
        const uint4* src = (const uint4*)row;
        #pragma unroll
        for (int q = 0; q < 6; q++) {
            int idx = j + q * IN_F;
            if (idx < KTOT * 2 / 16) gdst[idx] = src[idx];
        }
    } else {
        const int i = blockIdx.x - B_DIM;
        const int ij = i * IN_F + j;
        float bwv = bw[ij], pwv = pw[ij], swv = sw[ij];
        __half* dst = row + j * KF;
        dst[0] = __float2half_rn(bwv * pwv);
        dst[1] = __float2half_rn(bwv);
        const float4* c4 = (const float4*)(coef + (size_t)ij * NCOEF);
        #pragma unroll
        for (int q = 0; q < 5; q++) {
            float4 c = c4[q];
            dst[2 + q * 4 + 0] = __float2half_rn(swv * c.x);
            dst[2 + q * 4 + 1] = __float2half_rn(swv * c.y);
            dst[2 + q * 4 + 2] = __float2half_rn(swv * c.z);
            dst[2 + q * 4 + 3] = __float2half_rn(swv * c.w);
        }
        __syncthreads();
        uint4* gdst = (uint4*)(g_w + (size_t)i * KTOT);
        const uint4* src = (const uint4*)row;
        #pragma unroll
        for (int q = 0; q < 6; q++) {
            int idx = j + q * IN_F;
            if (idx < KTOT * 2 / 16) gdst[idx] = src[idx];
        }
    }
}

// ---------- kernel 2: mma.sync fp16 GEMM, warp 64x64, KT=64, 3-stage cp.async ----------
__global__ __launch_bounds__(256) void gemm_kernel() {
    extern __shared__ char smem[];
    const uint32_t sb = smem_u32(smem);
    const int tid  = threadIdx.x;
    const int lane = tid & 31;
    const int warp = tid >> 5;
    const int wm = warp >> 2;    // 0..1  (M)
    const int wn = warp & 3;     // 0..3  (N)
    const int lr = lane >> 2;    // 0..7
    const int lc = lane & 3;     // 0..3
    const int bm = blockIdx.x, bn = blockIdx.y, ks = blockIdx.z;

    const char* Abase = (const char*)(g_feat + (size_t)bm * MT * KTOT + (size_t)ks * KCH);
    const char* Bbase = (const char*)(g_w    + (size_t)bn * NT * KTOT + (size_t)ks * KCH);

    // per stage: A 128 rows x 8 chunks = 1024, B 256 x 8 = 2048; 4+8 per thread
    #define LOAD_STAGE(it) do {                                                    \
        const int buf_ = (it) % NSTAGE;                                            \
        const uint32_t as_ = sb + buf_ * STG;                                      \
        const uint32_t bs_ = as_ + A_BYTES;                                        \
        _Pragma("unroll")                                                          \
        for (int n_ = 0; n_ < 4; n_++) {                                           \
            int ch_ = tid + n_ * 256;                                              \
            int row_ = ch_ >> 3, c_ = ch_ & 7;                                     \
            cpa16(as_ + row_ * ROWB + c_ * 16,                                     \
                  Abase + ((size_t)row_ * KTOT + (size_t)(it) * KT) * 2 + c_ * 16);\
        }                                                                          \
        _Pragma("unroll")                                                          \
        for (int n_ = 0; n_ < 8; n_++) {                                           \
            int ch_ = tid + n_ * 256;                                              \
            int row_ = ch_ >> 3, c_ = ch_ & 7;                                     \
            cpa16(bs_ + row_ * ROWB + c_ * 16,                                     \
                  Bbase + ((size_t)row_ * KTOT + (size_t)(it) * KT) * 2 + c_ * 16);\
        }                                                                          \
        asm volatile("cp.async.commit_group;" ::: "memory");                       \
    } while (0)

    float acc[4][8][4];
    #pragma unroll
    for (int mt = 0; mt < 4; mt++)
        #pragma unroll
        for (int nt = 0; nt < 8; nt++)
            #pragma unroll
            for (int q = 0; q < 4; q++) acc[mt][nt][q] = 0.0f;

    LOAD_STAGE(0);
    LOAD_STAGE(1);

    // A x4: matrices [r0-7 k0-7, r8-15 k0-7, r0-7 k8-15, r8-15 k8-15]
    const int a_row_in = ((lane >> 3) & 1) * 8 + (lane & 7);
    const int a_col16  = (lane >> 4) * 16;
    // B x4: matrices [n0-7 k0-7, n0-7 k8-15, n8-15 k0-7, n8-15 k8-15]
    const int b_g      = lane >> 3;
    const int b_row_in = (b_g >> 1) * 8 + (lane & 7);
    const int b_col16  = (b_g & 1) * 16;

    const uint32_t a_off = (uint32_t)((wm * 64 + a_row_in) * ROWB) + a_col16;
    const uint32_t b_off = (uint32_t)(A_BYTES + (wn * 64 + b_row_in) * ROWB) + b_col16;

    for (int it = 0; it < NIT; it++) {
        asm volatile("cp.async.wait_group 1;" ::: "memory");
        __syncthreads();

        if (it + 2 < NIT) LOAD_STAGE(it + 2);
        else              asm volatile("cp.async.commit_group;" ::: "memory");

        const int buf = it % NSTAGE;
        const uint32_t a_base = sb + buf * STG + a_off;
        const uint32_t b_base = sb + buf * STG + b_off;

        #pragma unroll
        for (int kk = 0; kk < 4; kk++) {        // 4 x K=16 steps (32B each)
            uint32_t af[4][4], bf[4][4];
            #pragma unroll
            for (int mt = 0; mt < 4; mt++)
                ldsm_x4(af[mt], a_base + mt * (16 * ROWB) + kk * 32);
            #pragma unroll
            for (int np = 0; np < 4; np++)
                ldsm_x4(bf[np], b_base + np * (16 * ROWB) + kk * 32);
            #pragma unroll
            for (int mt = 0; mt < 4; mt++)
                #pragma unroll
                for (int nt = 0; nt < 8; nt++)
                    mma_f16(acc[mt][nt], af[mt], &bf[nt >> 1][(nt & 1) * 2]);
        }
    }

    // epilogue: write partial sums
    float* base = g_partial + (size_t)ks * B_DIM * OUT_F;
    #pragma unroll
    for (int mt = 0; mt < 4; mt++) {
        #pragma unroll
        for (int nt = 0; nt < 8; nt++) {
            int row = bm * MT + wm * 64 + mt * 16 + lr;
            int col = bn * NT + wn * 64 + nt * 8 + 2 * lc;
            float2 v0 = make_float2(acc[mt][nt][0], acc[mt][nt][1]);
            float2 v1 = make_float2(acc[mt][nt][2], acc[mt][nt][3]);
            *(float2*)(base + (size_t)row * OUT_F + col) = v0;
            *(float2*)(base + (size_t)(row + 8) * OUT_F + col) = v1;
        }
    }
}

// ---------- kernel 3: deterministic 4-way reduce ----------
__global__ __launch_bounds__(256) void reduce_kernel(float* __restrict__ out) {
    const size_t n4 = (size_t)B_DIM * OUT_F / 4;
    size_t idx = (size_t)blockIdx.x * 256 + threadIdx.x;
    const float4* p = (const float4*)g_partial;
    float4 a = p[idx], b = p[idx + n4], c = p[idx + 2 * n4], d = p[idx + 3 * n4];
    float4 r;
    r.x = (a.x + b.x) + (c.x + d.x);
    r.y = (a.y + b.y) + (c.y + d.y);
    r.z = (a.z + b.z) + (c.z + d.z);
    r.w = (a.w + b.w) + (c.w + d.w);
    ((float4*)out)[idx] = r;
}

extern "C" void kernel_launch(void* const* d_in, const int* in_sizes, int n_in,
                              void* d_out, int out_size) {
    const float* x    = (const float*)d_in[0];
    const float* pw   = (const float*)d_in[1];
    const float* bw   = (const float*)d_in[2];
    const float* sw   = (const float*)d_in[3];
    const float* coef = (const float*)d_in[4];
    float* out = (float*)d_out;

    prep_kernel<<<B_DIM + OUT_F, IN_F>>>(x, pw, bw, sw, coef);

    cudaFuncSetAttribute(gemm_kernel, cudaFuncAttributeMaxDynamicSharedMemorySize, SMEM_TOTAL);
    dim3 grid(B_DIM / MT, OUT_F / NT, KSPLIT);
    gemm_kernel<<<grid, 256, SMEM_TOTAL>>>();

    reduce_kernel<<<(B_DIM * OUT_F / 4) / 256, 256>>>(out);
}